// round 16
// baseline (speedup 1.0000x reference)
#include <cuda_runtime.h>
#include <cuda.h>
#include <cuda_bf16.h>
#include <cstddef>
#include <cstdint>

#define BATCH 4
#define HW 16384   // 128*128

typedef unsigned short ushort_t;

// ---------------- scratch (device globals; no allocation allowed) ----------------
__device__ ushort_t g_qh  [(size_t)BATCH*256*HW];   // q bf16 hi (attn + pool input)
__device__ ushort_t g_ql  [(size_t)BATCH*256*HW];   // q bf16 lo
__device__ ushort_t g_ctxh[(size_t)BATCH*256*HW];   // ctx bf16 hi
__device__ ushort_t g_ctxl[(size_t)BATCH*256*HW];   // ctx bf16 lo
__device__ ushort_t g_fh  [(size_t)BATCH*512*HW];   // feats bf16 hi
__device__ ushort_t g_fl  [(size_t)BATCH*512*HW];   // feats bf16 lo
__device__ ushort_t g_keyh[(size_t)BATCH*256*112];  // pooled q bf16 hi [c][112]
__device__ ushort_t g_keyl[(size_t)BATCH*256*112];
__device__ ushort_t g_valth[(size_t)BATCH*112*256]; // pooled v bf16 hi [s][c]
__device__ ushort_t g_valtl[(size_t)BATCH*112*256];
__device__ float    g_fpool[(size_t)BATCH*512*112]; // pooled feats fp32 [b][c][112]
__device__ float    g_weff[512*256];
__device__ float    g_beff[512];
__device__ ushort_t g_A0h[256*512], g_A0l[256*512];     // w_kq hi/lo
__device__ ushort_t g_A1h[512*768], g_A1l[512*768];     // [Weff | Wbot_right] hi/lo

// ============================ helpers ===============================
__device__ __forceinline__ uint32_t smem_u32(const void* p) {
    uint32_t a;
    asm("{ .reg .u64 t; cvta.to.shared.u64 t, %1; cvt.u32.u64 %0, t; }" : "=r"(a) : "l"(p));
    return a;
}
__device__ __forceinline__ uint32_t swz(uint32_t o) { return o ^ ((o >> 3) & 0x70); }

__device__ __forceinline__ void ldsm4(uint32_t* r, uint32_t addr) {
    asm volatile("ldmatrix.sync.aligned.m8n8.x4.shared.b16 {%0,%1,%2,%3}, [%4];"
                 : "=r"(r[0]), "=r"(r[1]), "=r"(r[2]), "=r"(r[3]) : "r"(addr));
}
__device__ __forceinline__ void ldsm4t(uint32_t* r, uint32_t addr) {
    asm volatile("ldmatrix.sync.aligned.m8n8.x4.trans.shared.b16 {%0,%1,%2,%3}, [%4];"
                 : "=r"(r[0]), "=r"(r[1]), "=r"(r[2]), "=r"(r[3]) : "r"(addr));
}
__device__ __forceinline__ void mma16816(float* c, const uint32_t* a, uint32_t b0, uint32_t b1) {
    asm volatile(
        "mma.sync.aligned.m16n8k16.row.col.f32.bf16.bf16.f32 "
        "{%0,%1,%2,%3}, {%4,%5,%6,%7}, {%8,%9}, {%0,%1,%2,%3};"
        : "+f"(c[0]), "+f"(c[1]), "+f"(c[2]), "+f"(c[3])
        : "r"(a[0]), "r"(a[1]), "r"(a[2]), "r"(a[3]), "r"(b0), "r"(b1));
}
__device__ __forceinline__ void bf16split(float x, unsigned short& h, unsigned short& l) {
    __nv_bfloat16 hb = __float2bfloat16_rn(x);
    float r = x - __bfloat162float(hb);
    __nv_bfloat16 lb = __float2bfloat16_rn(r);
    h = __bfloat16_as_ushort(hb);
    l = __bfloat16_as_ushort(lb);
}
__device__ __forceinline__ float bf16pair(unsigned short h, unsigned short l) {
    return __uint_as_float((uint32_t)h << 16) + __uint_as_float((uint32_t)l << 16);
}
__device__ __forceinline__ void cp16(uint32_t s, const void* g) {
    asm volatile("cp.async.cg.shared.global [%0], [%1], 16;"
                 :: "r"(s), "l"(__cvta_generic_to_global(g)) : "memory");
}
__device__ __forceinline__ void cp_commit() {
    asm volatile("cp.async.commit_group;" ::: "memory");
}
template<int N>
__device__ __forceinline__ void cp_wait() {
    asm volatile("cp.async.wait_group %0;" :: "n"(N) : "memory");
}
// -------- TMA + mbarrier (sm_90 base features) --------
__device__ __forceinline__ void tma2d(uint32_t smem, const CUtensorMap* m, int x, int y, uint32_t mb) {
    asm volatile("cp.async.bulk.tensor.2d.shared::cta.global.tile.mbarrier::complete_tx::bytes "
                 "[%0], [%1, {%2, %3}], [%4];"
                 :: "r"(smem), "l"(m), "r"(x), "r"(y), "r"(mb) : "memory");
}
__device__ __forceinline__ void mbar_init(uint32_t a, uint32_t cnt) {
    asm volatile("mbarrier.init.shared.b64 [%0], %1;" :: "r"(a), "r"(cnt) : "memory");
}
__device__ __forceinline__ void mbar_expect_tx(uint32_t a, uint32_t bytes) {
    asm volatile("mbarrier.arrive.expect_tx.shared.b64 _, [%0], %1;" :: "r"(a), "r"(bytes) : "memory");
}
__device__ __forceinline__ void mbar_wait(uint32_t a, uint32_t parity) {
    asm volatile(
        "{\n\t.reg .pred P;\n\t"
        "LAB%=: mbarrier.try_wait.parity.acquire.cta.shared::cta.b64 P, [%0], %1, 0x989680;\n\t"
        "@!P bra LAB%=;\n\t}"
        :: "r"(a), "r"(parity) : "memory");
}
__device__ __forceinline__ void fence_proxy_async_cta() {
    asm volatile("fence.proxy.async.shared::cta;" ::: "memory");
}

// ---------------- W_eff = W_bot[:, :512] @ W_out ; b_eff = W_bot[:,:512]@b_out + b_bot
__global__ void weff_kernel(const float* __restrict__ w_out, const float* __restrict__ b_out,
                            const float* __restrict__ w_bot, const float* __restrict__ b_bot)
{
    int m = blockIdx.x;      // 0..511
    int k = threadIdx.x;     // 0..255
    float a0 = 0.f, a1 = 0.f, a2 = 0.f, a3 = 0.f;
    for (int j = 0; j < 512; j += 4) {
        a0 += w_bot[m*1024 + j + 0] * w_out[(j + 0)*256 + k];
        a1 += w_bot[m*1024 + j + 1] * w_out[(j + 1)*256 + k];
        a2 += w_bot[m*1024 + j + 2] * w_out[(j + 2)*256 + k];
        a3 += w_bot[m*1024 + j + 3] * w_out[(j + 3)*256 + k];
    }
    g_weff[m*256 + k] = (a0 + a1) + (a2 + a3);
    if (k == 0) {
        float bb = b_bot[m];
        for (int j = 0; j < 512; j++) bb += w_bot[m*1024 + j] * b_out[j];
        g_beff[m] = bb;
    }
}

// ---------------- operand pre-split kernels (fp32 -> bf16 hi/lo) ------------------
__global__ void splitA0_kernel(const float* __restrict__ w_kq)
{
    int m = blockIdx.x;      // 0..255
    for (int k = threadIdx.x; k < 512; k += 256) {
        unsigned short h, l; bf16split(w_kq[m*512 + k], h, l);
        g_A0h[m*512 + k] = h; g_A0l[m*512 + k] = l;
    }
}
__global__ void splitA1_kernel(const float* __restrict__ w_bot)
{
    int m = blockIdx.x;
    for (int k = threadIdx.x; k < 768; k += 256) {
        float v = (k < 256) ? g_weff[m*256 + k] : w_bot[m*1024 + 256 + k];
        unsigned short h, l; bf16split(v, h, l);
        g_A1h[m*768 + k] = h; g_A1l[m*768 + k] = l;
    }
}
__global__ void split_feats_kernel(const float* __restrict__ f)
{
    const size_t N4 = (size_t)BATCH*512*HW/4;
    for (size_t t = (size_t)blockIdx.x*blockDim.x + threadIdx.x;
         t < N4; t += (size_t)gridDim.x*blockDim.x) {
        float4 v = ((const float4*)f)[t];
        unsigned short h0,h1,h2,h3,l0,l1,l2,l3;
        bf16split(v.x,h0,l0); bf16split(v.y,h1,l1);
        bf16split(v.z,h2,l2); bf16split(v.w,h3,l3);
        ((uint2*)g_fh)[t] = make_uint2((uint32_t)h0 | ((uint32_t)h1<<16),
                                       (uint32_t)h2 | ((uint32_t)h3<<16));
        ((uint2*)g_fl)[t] = make_uint2((uint32_t)l0 | ((uint32_t)l1<<16),
                                       (uint32_t)l2 | ((uint32_t)l3<<16));
    }
}

// ================= TMA-fed mma.sync bf16 3-split GEMM =============================
// CTA tile 128m x 256n, 16 warps (each 64m x 32n), BK=64, 2-stage TMA pipeline.
// MODE 0: A = w_kq (256m), B = feats -> q = relu(.+b_kq) written as bf16 hi/lo only.
// MODE 1: A = [Weff | Wbot_right] (512m), B = [ctx; feats] -> out fp32.
#define A_BYTES 16384
#define STAGE_B 98304
#define CHUNK_TX 98304u

template<int MODE>
__global__ __launch_bounds__(512, 1)
void mma_gemm_kernel(const __grid_constant__ CUtensorMap tmAh,
                     const __grid_constant__ CUtensorMap tmAl,
                     const __grid_constant__ CUtensorMap tmBh,
                     const __grid_constant__ CUtensorMap tmBl,
                     const __grid_constant__ CUtensorMap tmB2h,
                     const __grid_constant__ CUtensorMap tmB2l,
                     const float* __restrict__ b_kq,
                     float* __restrict__ out)
{
    constexpr int K  = (MODE == 0) ? 512 : 768;
    constexpr int NC = K / 64;
    extern __shared__ char dyn[];
    char* base = (char*)(((uintptr_t)dyn + 1023) & ~(uintptr_t)1023);
    __shared__ alignas(8) unsigned long long s_mbar[2];

    const int tid  = threadIdx.x;
    const int wid  = tid >> 5, lane = tid & 31;
    const int wm   = wid & 1,  wn   = wid >> 1;       // wn 0..7
    const int m0   = blockIdx.x * 128;                // x = m-tile (L2 reuse of B)
    const int n0   = blockIdx.y * 256;
    const int b    = blockIdx.z;
    const int lr   = lane & 15, lh = lane >> 4;

    if (tid == 0) { mbar_init(smem_u32(&s_mbar[0]), 1); mbar_init(smem_u32(&s_mbar[1]), 1); }
    __syncthreads();
    if (tid == 0) fence_proxy_async_cta();
    __syncthreads();

    float acc[4][4][4];
#pragma unroll
    for (int i = 0; i < 4; i++)
#pragma unroll
        for (int j = 0; j < 4; j++)
#pragma unroll
            for (int r = 0; r < 4; r++) acc[i][j][r] = 0.f;

    auto issue_chunk = [&](int c) {
        const int buf = c & 1;
        const int k0  = c * 64;
        uint32_t sa = smem_u32(base + buf * STAGE_B);
        uint32_t mb = smem_u32(&s_mbar[buf]);
        mbar_expect_tx(mb, CHUNK_TX);
        tma2d(sa,           &tmAh, k0, m0, mb);
        tma2d(sa + A_BYTES, &tmAl, k0, m0, mb);
        const CUtensorMap *bh, *bl; int y;
        if (MODE == 0)     { bh = &tmBh;  bl = &tmBl;  y = b*512 + k0; }
        else if (k0 < 256) { bh = &tmBh;  bl = &tmBl;  y = b*256 + k0; }        // ctx
        else               { bh = &tmB2h; bl = &tmB2l; y = b*512 + (k0 - 256); } // feats
#pragma unroll
        for (int s = 0; s < 4; s++) {
            tma2d(sa + 2*A_BYTES + s*8192,         bh, n0 + 64*s, y, mb);
            tma2d(sa + 2*A_BYTES + 32768 + s*8192, bl, n0 + 64*s, y, mb);
        }
    };

    auto compute = [&](int c) {
        uint32_t aH = smem_u32(base + (c & 1) * STAGE_B);
        uint32_t aL = aH + A_BYTES;
        uint32_t bH = aL + A_BYTES;
        uint32_t bL = bH + 32768;
#pragma unroll
        for (int kk = 0; kk < 4; kk++) {
            const int k0 = kk * 16;
            uint32_t ah[4][4], al[4][4];
#pragma unroll
            for (int mi = 0; mi < 4; mi++) {
                int row = wm*64 + mi*16 + lr;
                uint32_t off = swz((uint32_t)(row*128 + (k0 + lh*8)*2));
                ldsm4(ah[mi], aH + off);
                ldsm4(al[mi], aL + off);
            }
            uint32_t bh[2][4], bl[2][4];
#pragma unroll
            for (int p = 0; p < 2; p++) {
                int n = wn*32 + p*16 + lh*8;
                uint32_t off = (uint32_t)((n >> 6) * 8192)
                             + swz((uint32_t)((k0 + lr)*128 + (n & 63)*2));
                ldsm4t(bh[p], bH + off);
                ldsm4t(bl[p], bL + off);
            }
#pragma unroll
            for (int mi = 0; mi < 4; mi++)
#pragma unroll
                for (int nj = 0; nj < 4; nj++) {
                    int p = nj >> 1, q = (nj & 1) * 2;
                    mma16816(acc[mi][nj], ah[mi], bh[p][q], bh[p][q+1]);
                }
#pragma unroll
            for (int mi = 0; mi < 4; mi++)
#pragma unroll
                for (int nj = 0; nj < 4; nj++) {
                    int p = nj >> 1, q = (nj & 1) * 2;
                    mma16816(acc[mi][nj], ah[mi], bl[p][q], bl[p][q+1]);
                }
#pragma unroll
            for (int mi = 0; mi < 4; mi++)
#pragma unroll
                for (int nj = 0; nj < 4; nj++) {
                    int p = nj >> 1, q = (nj & 1) * 2;
                    mma16816(acc[mi][nj], al[mi], bh[p][q], bh[p][q+1]);
                }
        }
    };

    if (tid == 0) { issue_chunk(0); issue_chunk(1); }
    for (int c = 0; c < NC; c++) {
        mbar_wait(smem_u32(&s_mbar[c & 1]), (uint32_t)((c >> 1) & 1));
        compute(c);
        __syncthreads();
        if (tid == 0 && c + 2 < NC) issue_chunk(c + 2);
    }

    // ---- epilogue: frags -> smem [128][260] -> coalesced gmem + bias/relu ----
    float* sD = (float*)base;
    {
        int tq = lane & 3, tr = lane >> 2;
#pragma unroll
        for (int mi = 0; mi < 4; mi++)
#pragma unroll
            for (int nj = 0; nj < 4; nj++) {
                int r0 = wm*64 + mi*16 + tr;
                int cc = wn*32 + nj*8 + tq*2;
                *(float2*)&sD[(size_t)r0*260 + cc]     = make_float2(acc[mi][nj][0], acc[mi][nj][1]);
                *(float2*)&sD[(size_t)(r0+8)*260 + cc] = make_float2(acc[mi][nj][2], acc[mi][nj][3]);
            }
    }
    __syncthreads();
#pragma unroll
    for (int u = 0; u < 16; u++) {
        int idx4 = tid + 512 * u;            // 0..8191
        int m = idx4 >> 6;                   // 0..127
        int n = (idx4 & 63) * 4;             // 0..252
        int mg = m0 + m;
        if (MODE == 0) {
            float bias = b_kq[mg];
            float4 o;
            o.x = fmaxf(sD[(size_t)m*260 + n + 0] + bias, 0.f);
            o.y = fmaxf(sD[(size_t)m*260 + n + 1] + bias, 0.f);
            o.z = fmaxf(sD[(size_t)m*260 + n + 2] + bias, 0.f);
            o.w = fmaxf(sD[(size_t)m*260 + n + 3] + bias, 0.f);
            unsigned short h0,l0,h1,l1,h2,l2,h3,l3;
            bf16split(o.x,h0,l0); bf16split(o.y,h1,l1);
            bf16split(o.z,h2,l2); bf16split(o.w,h3,l3);
            size_t off = ((size_t)b*256 + mg)*HW + n0 + n;
            *(uint2*)(g_qh + off) = make_uint2((uint32_t)h0 | ((uint32_t)h1<<16),
                                               (uint32_t)h2 | ((uint32_t)h3<<16));
            *(uint2*)(g_ql + off) = make_uint2((uint32_t)l0 | ((uint32_t)l1<<16),
                                               (uint32_t)l2 | ((uint32_t)l3<<16));
        } else {
            float bias = g_beff[mg];
            float* dst = out + ((size_t)b*512 + mg) * HW;
            float4 o;
            o.x = fmaxf(sD[(size_t)m*260 + n + 0] + bias, 0.f);
            o.y = fmaxf(sD[(size_t)m*260 + n + 1] + bias, 0.f);
            o.z = fmaxf(sD[(size_t)m*260 + n + 2] + bias, 0.f);
            o.w = fmaxf(sD[(size_t)m*260 + n + 3] + bias, 0.f);
            *(float4*)(dst + n0 + n) = o;
        }
    }
}

// ---------------- adaptive pooling (q -> key, feats -> fpool) ---------------------
// grid (768, BATCH): cc<256 -> q channel; cc>=256 -> feats channel cc-256.
__global__ void poolqf_kernel()
{
    extern __shared__ float P[];   // [128][129]
    const int b = blockIdx.y, cc = blockIdx.x;
    const int t = threadIdx.x;     // 0..127
    const bool isq = (cc < 256);
    const ushort_t* sh;
    const ushort_t* sl;
    size_t off;
    if (isq) { sh = g_qh; sl = g_ql; off = ((size_t)b*256 + cc)*HW; }
    else     { sh = g_fh; sl = g_fl; off = ((size_t)b*512 + (cc-256))*HW; }

    for (int i = 0; i < 128; i++)
        P[i*129 + t] = bf16pair(sh[off + i*128 + t], sl[off + i*128 + t]);
    __syncthreads();
    { float s = 0.f;
      for (int j = 0; j < 128; j++) { s += P[t*129 + j]; P[t*129 + j] = s; } }
    __syncthreads();
    { float s = 0.f;
      for (int i = 0; i < 128; i++) { s += P[i*129 + t]; P[i*129 + t] = s; } }
    __syncthreads();
    if (t < 112) {
        float avg = 0.f;
        if (t < 110) {
            int sidx = t, sc, idx;
            if      (sidx == 0) { sc = 1; idx = 0; }
            else if (sidx < 10) { sc = 3; idx = sidx - 1; }
            else if (sidx < 46) { sc = 6; idx = sidx - 10; }
            else                { sc = 8; idx = sidx - 46; }
            int i = idx / sc, j = idx % sc;
            int h0 = (i*128)/sc, h1 = ((i+1)*128 + sc - 1)/sc;
            int w0 = (j*128)/sc, w1 = ((j+1)*128 + sc - 1)/sc;
            float s11 =                      P[(h1-1)*129 + (w1-1)];
            float s01 = (h0 > 0)           ? P[(h0-1)*129 + (w1-1)] : 0.f;
            float s10 = (w0 > 0)           ? P[(h1-1)*129 + (w0-1)] : 0.f;
            float s00 = (h0 > 0 && w0 > 0) ? P[(h0-1)*129 + (w0-1)] : 0.f;
            avg = (s11 - s01 - s10 + s00) / (float)((h1 - h0)*(w1 - w0));
        }
        if (isq) {
            unsigned short hh, ll; bf16split(avg, hh, ll);
            size_t o = ((size_t)b*256 + cc)*112 + t;
            g_keyh[o] = hh; g_keyl[o] = ll;
        } else {
            g_fpool[((size_t)b*512 + (cc-256))*112 + t] = avg;
        }
    }
}

// ---------------- v-pool: valt = Wv @ fpool + b_v  (pooling commuted) -------------
// grid (112, BATCH), 256 threads (c). valt [s][c] bf16 hi/lo, pad rows zero.
__global__ void vpool_kernel(const float* __restrict__ w_v, const float* __restrict__ b_v)
{
    __shared__ float fp[512];
    const int s = blockIdx.x, b = blockIdx.y;
    const int c = threadIdx.x;
    unsigned short hh = 0, ll = 0;
    if (s < 110) {
        fp[c]       = g_fpool[((size_t)b*512 + c)*112 + s];
        fp[c + 256] = g_fpool[((size_t)b*512 + c + 256)*112 + s];
        __syncthreads();
        float a0 = b_v[c], a1 = 0.f, a2 = 0.f, a3 = 0.f;
        const float* wr = w_v + (size_t)c*512;
#pragma unroll 4
        for (int k = 0; k < 512; k += 4) {
            a0 += wr[k+0] * fp[k+0];
            a1 += wr[k+1] * fp[k+1];
            a2 += wr[k+2] * fp[k+2];
            a3 += wr[k+3] * fp[k+3];
        }
        bf16split((a0 + a1) + (a2 + a3), hh, ll);
    }
    size_t o = ((size_t)b*112 + s)*256 + c;
    g_valth[o] = hh; g_valtl[o] = ll;
}

// ================= tensor-core attention (unchanged) ==============================
__global__ __launch_bounds__(256, 1)
void attn_kernel()
{
    extern __shared__ char smraw[];
    char* base = (char*)(((uintptr_t)smraw + 1023) & ~(uintptr_t)1023);
    float*    sim = (float*)base;                  // [128][120]
    ushort_t* Ah  = (ushort_t*)(base + 61440);     // [128][120]
    ushort_t* Al  = (ushort_t*)(base + 92160);
    char*     st1 = base + 61440;                  // phase1 staging, 2 x 17408
    char*     st2 = base + 122880;                 // valt staging,   2 x 8704

    const int b   = blockIdx.y;
    const int n0  = blockIdx.x * 128;
    const int tid = threadIdx.x;
    const int wid = tid >> 5, lane = tid & 31;
    const int lr  = lane & 15, lh = lane >> 4;
    const int mb  = (wid & 3) * 32;
    const int nb  = (wid >> 2) * 64;

    const ushort_t* gqh = g_qh + ((size_t)b*256)*HW + n0;
    const ushort_t* gql = g_ql + ((size_t)b*256)*HW + n0;
    const ushort_t* gkh = g_keyh + (size_t)b*256*112;
    const ushort_t* gkl = g_keyl + (size_t)b*256*112;

    {
        int i = tid;
        int stg  = i >> 7;
        int comp = (i >> 6) & 1;
        int row  = (i >> 2) & 15;
        int q8   = i & 3;
        *(uint2*)(st1 + stg*17408 + 8704 + comp*4352 + row*272 + 224 + q8*8)
            = make_uint2(0u, 0u);
    }
    __syncthreads();

    auto load_stage1 = [&](int c) {
        uint32_t sa = smem_u32(st1 + (c & 1) * 17408);
        const int c0 = c * 16;
#pragma unroll
        for (int u = 0; u < 4; u++) {
            int id = tid + 256*u;
            if (id < 512) {
                int comp = id >> 8, row = (id >> 4) & 15, c16 = id & 15;
                const ushort_t* src = (comp ? gql : gqh) + (size_t)(c0 + row)*HW + c16*8;
                cp16(sa + comp*4352 + row*272 + c16*16, src);
            } else if (id < 960) {
                int idx = id - 512;
                int comp = idx / 224;
                int rem  = idx - comp*224;
                int row  = rem / 14, c16 = rem - row*14;
                const ushort_t* src = (comp ? gkl : gkh) + (size_t)(c0 + row)*112 + c16*8;
                cp16(sa + 8704 + comp*4352 + row*272 + c16*16, src);
            }
        }
        cp_commit();
    };

    float acc[2][8][4];
#pragma unroll
    for (int i = 0; i < 2; i++)
#pragma unroll
        for (int j = 0; j < 8; j++)
#pragma unroll
            for (int r = 0; r < 4; r++) acc[i][j][r] = 0.f;

    load_stage1(0);
    for (int c = 0; c < 16; c++) {
        if (c + 1 < 16) { load_stage1(c + 1); cp_wait<1>(); }
        else            { cp_wait<0>(); }
        __syncthreads();
        uint32_t qa = smem_u32(st1 + (c & 1)*17408);
        uint32_t ka = qa + 8704;
        uint32_t ah[2][4], al[2][4], r4[4];
#pragma unroll
        for (int mi = 0; mi < 2; mi++) {
            uint32_t off = lr*272 + (mb + mi*16 + lh*8)*2;
            ldsm4t(r4, qa + off);
            ah[mi][0]=r4[0]; ah[mi][1]=r4[2]; ah[mi][2]=r4[1]; ah[mi][3]=r4[3];
            ldsm4t(r4, qa + 4352 + off);
            al[mi][0]=r4[0]; al[mi][1]=r4[2]; al[mi][2]=r4[1]; al[mi][3]=r4[3];
        }
        uint32_t bh[4][4], bl[4][4];
#pragma unroll
        for (int t = 0; t < 4; t++) {
            uint32_t off = lr*272 + (nb + t*16 + lh*8)*2;
            ldsm4t(bh[t], ka + off);
            ldsm4t(bl[t], ka + 4352 + off);
        }
#pragma unroll
        for (int mi = 0; mi < 2; mi++)
#pragma unroll
            for (int nj = 0; nj < 8; nj++) {
                int p = nj >> 1, q = (nj & 1)*2;
                mma16816(acc[mi][nj], ah[mi], bh[p][q], bh[p][q+1]);
            }
#pragma unroll
        for (int mi = 0; mi < 2; mi++)
#pragma unroll
            for (int nj = 0; nj < 8; nj++) {
                int p = nj >> 1, q = (nj & 1)*2;
                mma16816(acc[mi][nj], ah[mi], bl[p][q], bl[p][q+1]);
            }
#pragma unroll
        for (int mi = 0; mi < 2; mi++)
#pragma unroll
            for (int nj = 0; nj < 8; nj++) {
                int p = nj >> 1, q = (nj & 1)*2;
                mma16816(acc[mi][nj], al[mi], bh[p][q], bh[p][q+1]);
            }
        __syncthreads();
    }

#pragma unroll
    for (int mi = 0; mi < 2; mi++)
#pragma unroll
        for (int nj = 0; nj < 8; nj++) {
            int col = nb + nj*8 + (lane & 3)*2;
            if (col < 112) {
                int m = mb + mi*16 + (lane >> 2);
                sim[m*120 + col]       = acc[mi][nj][0] * 0.0625f;
                sim[m*120 + col + 1]   = acc[mi][nj][1] * 0.0625f;
                sim[(m+8)*120 + col]   = acc[mi][nj][2] * 0.0625f;
                sim[(m+8)*120 + col+1] = acc[mi][nj][3] * 0.0625f;
            }
        }
    __syncthreads();

    {
        int row = tid >> 1, half = tid & 1;
        float* r = sim + row*120;
        int s0 = half*55, s1 = s0 + 55;
        float mx = -1e30f;
        for (int s = s0; s < s1; s++) mx = fmaxf(mx, r[s]);
        mx = fmaxf(mx, __shfl_xor_sync(0xFFFFFFFFu, mx, 1));
        float sum = 0.f;
        for (int s = s0; s < s1; s++) { float e = __expf(r[s] - mx); r[s] = e; sum += e; }
        sum += __shfl_xor_sync(0xFFFFFFFFu, sum, 1);
        float inv = 1.f / sum;
        for (int s = s0; s < s1; s++) r[s] *= inv;
        if (half == 0) { r[110] = 0.f; r[111] = 0.f; }
    }
    __syncthreads();

    {
        int row = tid >> 1, h0 = (tid & 1)*56;
        for (int s = h0; s < h0 + 56; s++) {
            unsigned short hh, ll;
            bf16split(sim[row*120 + s], hh, ll);
            Ah[row*120 + s] = hh;
            Al[row*120 + s] = ll;
        }
    }
    __syncthreads();

    const ushort_t* gvh = g_valth + (size_t)b*112*256;
    const ushort_t* gvl = g_valtl + (size_t)b*112*256;
    const uint32_t Aaddr = smem_u32(Ah);
    const size_t cbase = (size_t)b*256*HW + n0;

    for (int hp = 0; hp < 2; hp++) {
        auto load_stage2 = [&](int s) {
            uint32_t sa = smem_u32(st2 + (s & 1)*8704);
            const int s0 = s * 16;
#pragma unroll
            for (int u = 0; u < 2; u++) {
                int id = tid + 256*u;         // 0..511
                int comp = id >> 8, row = (id >> 4) & 15, c16 = id & 15;
                const ushort_t* src = (comp ? gvl : gvh)
                    + (size_t)(s0 + row)*256 + hp*128 + c16*8;
                cp16(sa + comp*4352 + row*272 + c16*16, src);
            }
            cp_commit();
        };

        float acc2[2][8][4];
#pragma unroll
        for (int i = 0; i < 2; i++)
#pragma unroll
            for (int j = 0; j < 8; j++)
#pragma unroll
                for (int r = 0; r < 4; r++) acc2[i][j][r] = 0.f;

        load_stage2(0);
        for (int s = 0; s < 7; s++) {
            if (s + 1 < 7) { load_stage2(s + 1); cp_wait<1>(); }
            else           { cp_wait<0>(); }
            __syncthreads();
            uint32_t va = smem_u32(st2 + (s & 1)*8704);
            uint32_t ah2[2][4], al2[2][4];
#pragma unroll
            for (int mi = 0; mi < 2; mi++) {
                uint32_t off = (uint32_t)((mb + mi*16 + lr)*240 + (s*16 + lh*8)*2);
                ldsm4(ah2[mi], Aaddr + off);
                ldsm4(al2[mi], Aaddr + 30720 + off);
            }
            uint32_t bh2[4][4], bl2[4][4];
#pragma unroll
            for (int t = 0; t < 4; t++) {
                uint32_t off = lr*272 + (nb + t*16 + lh*8)*2;
                ldsm4t(bh2[t], va + off);
                ldsm4t(bl2[t], va + 4352 + off);
            }
#pragma unroll
            for (int mi = 0; mi < 2; mi++)
#pragma unroll
                for (int nj = 0; nj < 8; nj++) {
                    int p = nj >> 1, q = (nj & 1)*2;
                    mma16816(acc2[mi][nj], ah2[mi], bh2[p][q], bh2[p][q+1]);
                }
#pragma unroll
            for (int mi = 0; mi < 2; mi++)
#pragma unroll
                for (int nj = 0; nj < 8; nj++) {
                    int p = nj >> 1, q = (nj & 1)*2;
                    mma16816(acc2[mi][nj], ah2[mi], bl2[p][q], bl2[p][q+1]);
                }
#pragma unroll
            for (int mi = 0; mi < 2; mi++)
#pragma unroll
                for (int nj = 0; nj < 8; nj++) {
                    int p = nj >> 1, q = (nj & 1)*2;
                    mma16816(acc2[mi][nj], al2[mi], bh2[p][q], bh2[p][q+1]);
                }
            __syncthreads();
        }

#pragma unroll
        for (int mi = 0; mi < 2; mi++)
#pragma unroll
            for (int nj = 0; nj < 8; nj++) {
                int m = mb + mi*16 + (lane >> 2);
                int cch = hp*128 + nb + nj*8 + (lane & 3)*2;
                unsigned short hh, ll;
#pragma unroll
                for (int r = 0; r < 4; r++) {
                    int mm = m + (r >> 1)*8;
                    int cc = cch + (r & 1);
                    bf16split(acc2[mi][nj][r], hh, ll);
                    size_t o = cbase + (size_t)cc*HW + mm;
                    g_ctxh[o] = hh;
                    g_ctxl[o] = ll;
                }
            }
    }
}

// ------------------------- host-side TMA descriptor setup -------------------------
typedef CUresult (*PFN_encodeTiled)(
    CUtensorMap*, CUtensorMapDataType, unsigned int, void*,
    const unsigned long long*, const unsigned long long*,
    const unsigned int*, const unsigned int*,
    CUtensorMapInterleave, CUtensorMapSwizzle, CUtensorMapL2promotion,
    CUtensorMapFloatOOBfill);

static void enc2d(PFN_encodeTiled f, CUtensorMap* m, void* p,
                  unsigned long long rows, unsigned long long cols,
                  unsigned int box_inner, unsigned int box_rows)
{
    unsigned long long dims[2]    = {cols, rows};
    unsigned long long strides[1] = {cols * 2ull};     // u16
    unsigned int box[2]  = {box_inner, box_rows};
    unsigned int es[2]   = {1, 1};
    f(m, CU_TENSOR_MAP_DATA_TYPE_UINT16, 2, p, dims, strides, box, es,
      CU_TENSOR_MAP_INTERLEAVE_NONE, CU_TENSOR_MAP_SWIZZLE_128B,
      CU_TENSOR_MAP_L2_PROMOTION_L2_128B, CU_TENSOR_MAP_FLOAT_OOB_FILL_NONE);
}

// ----------------------------------------------------------------------------------
extern "C" void kernel_launch(void* const* d_in, const int* in_sizes, int n_in,
                              void* d_out, int out_size)
{
    const float* feats = (const float*)d_in[0];
    const float* w_kq  = (const float*)d_in[1];
    const float* b_kq  = (const float*)d_in[2];
    const float* w_v   = (const float*)d_in[3];
    const float* b_v   = (const float*)d_in[4];
    const float* w_out = (const float*)d_in[5];
    const float* b_out = (const float*)d_in[6];
    const float* w_bot = (const float*)d_in[7];
    const float* b_bot = (const float*)d_in[8];
    float* out = (float*)d_out;

    PFN_encodeTiled encf = nullptr;
    {
        void* fp = nullptr;
        cudaDriverEntryPointQueryResult st;
        cudaGetDriverEntryPoint("cuTensorMapEncodeTiled", &fp, cudaEnableDefault, &st);
        encf = (PFN_encodeTiled)fp;
    }
    void *pA0h, *pA0l, *pA1h, *pA1l, *pFh, *pFl, *pCh, *pCl;
    cudaGetSymbolAddress(&pA0h, g_A0h);  cudaGetSymbolAddress(&pA0l, g_A0l);
    cudaGetSymbolAddress(&pA1h, g_A1h);  cudaGetSymbolAddress(&pA1l, g_A1l);
    cudaGetSymbolAddress(&pFh,  g_fh);   cudaGetSymbolAddress(&pFl,  g_fl);
    cudaGetSymbolAddress(&pCh,  g_ctxh); cudaGetSymbolAddress(&pCl,  g_ctxl);

    CUtensorMap mA0h, mA0l, mA1h, mA1l, mFh, mFl, mCh, mCl;
    enc2d(encf, &mA0h, pA0h, 256, 512, 64, 128);
    enc2d(encf, &mA0l, pA0l, 256, 512, 64, 128);
    enc2d(encf, &mA1h, pA1h, 512, 768, 64, 128);
    enc2d(encf, &mA1l, pA1l, 512, 768, 64, 128);
    enc2d(encf, &mFh,  pFh,  (unsigned long long)BATCH*512, HW, 64, 64);
    enc2d(encf, &mFl,  pFl,  (unsigned long long)BATCH*512, HW, 64, 64);
    enc2d(encf, &mCh,  pCh,  (unsigned long long)BATCH*256, HW, 64, 64);
    enc2d(encf, &mCl,  pCl,  (unsigned long long)BATCH*256, HW, 64, 64);

    const int pool_smem = 128*129*4;                 // 66048
    const int attn_smem = 157696 + 1024;             // 158720
    const int mma_smem  = 2*STAGE_B + 1024;          // 197632
    cudaFuncSetAttribute(poolqf_kernel, cudaFuncAttributeMaxDynamicSharedMemorySize, pool_smem);
    cudaFuncSetAttribute(attn_kernel, cudaFuncAttributeMaxDynamicSharedMemorySize, attn_smem);
    cudaFuncSetAttribute(mma_gemm_kernel<0>, cudaFuncAttributeMaxDynamicSharedMemorySize, mma_smem);
    cudaFuncSetAttribute(mma_gemm_kernel<1>, cudaFuncAttributeMaxDynamicSharedMemorySize, mma_smem);

    weff_kernel<<<512, 256>>>(w_out, b_out, w_bot, b_bot);
    splitA0_kernel<<<256, 256>>>(w_kq);
    splitA1_kernel<<<512, 256>>>(w_bot);
    split_feats_kernel<<<4096, 256>>>(feats);
    mma_gemm_kernel<0><<<dim3(2, 64, BATCH), 512, mma_smem>>>(
        mA0h, mA0l, mFh, mFl, mFh, mFl, b_kq, out);
    poolqf_kernel<<<dim3(768, BATCH), 128, pool_smem>>>();
    vpool_kernel<<<dim3(112, BATCH), 256>>>(w_v, b_v);
    attn_kernel<<<dim3(128, BATCH), 256, attn_smem>>>();
    mma_gemm_kernel<1><<<dim3(4, 64, BATCH), 512, mma_smem>>>(
        mA1h, mA1l, mCh, mCl, mFh, mFl, b_kq, out);
}

// round 17
// speedup vs baseline: 1.0123x; 1.0123x over previous
#include <cuda_runtime.h>
#include <cuda.h>
#include <cuda_bf16.h>
#include <cstddef>
#include <cstdint>

#define BATCH 4
#define HW 16384   // 128*128

typedef unsigned short ushort_t;

// ---------------- scratch (device globals; no allocation allowed) ----------------
__device__ float    g_q   [(size_t)BATCH*256*HW];   // q fp32 (pool input)
__device__ ushort_t g_qh  [(size_t)BATCH*256*HW];   // q bf16 hi (attn input)
__device__ ushort_t g_ql  [(size_t)BATCH*256*HW];   // q bf16 lo
__device__ ushort_t g_ctxh[(size_t)BATCH*256*HW];   // ctx bf16 hi
__device__ ushort_t g_ctxl[(size_t)BATCH*256*HW];   // ctx bf16 lo
__device__ ushort_t g_fh  [(size_t)BATCH*512*HW];   // feats bf16 hi
__device__ ushort_t g_fl  [(size_t)BATCH*512*HW];   // feats bf16 lo
__device__ ushort_t g_keyh[(size_t)BATCH*256*112];  // pooled q bf16 hi [c][112]
__device__ ushort_t g_keyl[(size_t)BATCH*256*112];
__device__ ushort_t g_valth[(size_t)BATCH*112*256]; // pooled v bf16 hi [s][c]
__device__ ushort_t g_valtl[(size_t)BATCH*112*256];
__device__ float    g_fpool[(size_t)BATCH*112*512]; // pooled feats fp32 [b][s][c]
__device__ float    g_weff[512*256];
__device__ float    g_beff[512];
__device__ ushort_t g_A0h[256*512], g_A0l[256*512];     // w_kq hi/lo
__device__ ushort_t g_A1h[512*768], g_A1l[512*768];     // [Weff | Wbot_right] hi/lo

// ============================ helpers ===============================
__device__ __forceinline__ uint32_t smem_u32(const void* p) {
    uint32_t a;
    asm("{ .reg .u64 t; cvta.to.shared.u64 t, %1; cvt.u32.u64 %0, t; }" : "=r"(a) : "l"(p));
    return a;
}
__device__ __forceinline__ uint32_t swz(uint32_t o) { return o ^ ((o >> 3) & 0x70); }

__device__ __forceinline__ void ldsm4(uint32_t* r, uint32_t addr) {
    asm volatile("ldmatrix.sync.aligned.m8n8.x4.shared.b16 {%0,%1,%2,%3}, [%4];"
                 : "=r"(r[0]), "=r"(r[1]), "=r"(r[2]), "=r"(r[3]) : "r"(addr));
}
__device__ __forceinline__ void ldsm4t(uint32_t* r, uint32_t addr) {
    asm volatile("ldmatrix.sync.aligned.m8n8.x4.trans.shared.b16 {%0,%1,%2,%3}, [%4];"
                 : "=r"(r[0]), "=r"(r[1]), "=r"(r[2]), "=r"(r[3]) : "r"(addr));
}
__device__ __forceinline__ void mma16816(float* c, const uint32_t* a, uint32_t b0, uint32_t b1) {
    asm volatile(
        "mma.sync.aligned.m16n8k16.row.col.f32.bf16.bf16.f32 "
        "{%0,%1,%2,%3}, {%4,%5,%6,%7}, {%8,%9}, {%0,%1,%2,%3};"
        : "+f"(c[0]), "+f"(c[1]), "+f"(c[2]), "+f"(c[3])
        : "r"(a[0]), "r"(a[1]), "r"(a[2]), "r"(a[3]), "r"(b0), "r"(b1));
}
__device__ __forceinline__ void bf16split(float x, unsigned short& h, unsigned short& l) {
    __nv_bfloat16 hb = __float2bfloat16_rn(x);
    float r = x - __bfloat162float(hb);
    __nv_bfloat16 lb = __float2bfloat16_rn(r);
    h = __bfloat16_as_ushort(hb);
    l = __bfloat16_as_ushort(lb);
}
__device__ __forceinline__ void cp16(uint32_t s, const void* g) {
    asm volatile("cp.async.cg.shared.global [%0], [%1], 16;"
                 :: "r"(s), "l"(__cvta_generic_to_global(g)) : "memory");
}
__device__ __forceinline__ void cp_commit() {
    asm volatile("cp.async.commit_group;" ::: "memory");
}
template<int N>
__device__ __forceinline__ void cp_wait() {
    asm volatile("cp.async.wait_group %0;" :: "n"(N) : "memory");
}
// -------- TMA + mbarrier (sm_90 base features) --------
__device__ __forceinline__ void tma2d(uint32_t smem, const CUtensorMap* m, int x, int y, uint32_t mb) {
    asm volatile("cp.async.bulk.tensor.2d.shared::cta.global.tile.mbarrier::complete_tx::bytes "
                 "[%0], [%1, {%2, %3}], [%4];"
                 :: "r"(smem), "l"(m), "r"(x), "r"(y), "r"(mb) : "memory");
}
__device__ __forceinline__ void mbar_init(uint32_t a, uint32_t cnt) {
    asm volatile("mbarrier.init.shared.b64 [%0], %1;" :: "r"(a), "r"(cnt) : "memory");
}
__device__ __forceinline__ void mbar_expect_tx(uint32_t a, uint32_t bytes) {
    asm volatile("mbarrier.arrive.expect_tx.shared.b64 _, [%0], %1;" :: "r"(a), "r"(bytes) : "memory");
}
__device__ __forceinline__ void mbar_wait(uint32_t a, uint32_t parity) {
    asm volatile(
        "{\n\t.reg .pred P;\n\t"
        "LAB%=: mbarrier.try_wait.parity.acquire.cta.shared::cta.b64 P, [%0], %1, 0x989680;\n\t"
        "@!P bra LAB%=;\n\t}"
        :: "r"(a), "r"(parity) : "memory");
}
__device__ __forceinline__ void fence_proxy_async_cta() {
    asm volatile("fence.proxy.async.shared::cta;" ::: "memory");
}

// ---------------- W_eff = W_bot[:, :512] @ W_out ; b_eff = W_bot[:,:512]@b_out + b_bot
__global__ void weff_kernel(const float* __restrict__ w_out, const float* __restrict__ b_out,
                            const float* __restrict__ w_bot, const float* __restrict__ b_bot)
{
    int m = blockIdx.x;      // 0..511
    int k = threadIdx.x;     // 0..255
    float a0 = 0.f, a1 = 0.f, a2 = 0.f, a3 = 0.f;
    for (int j = 0; j < 512; j += 4) {
        a0 += w_bot[m*1024 + j + 0] * w_out[(j + 0)*256 + k];
        a1 += w_bot[m*1024 + j + 1] * w_out[(j + 1)*256 + k];
        a2 += w_bot[m*1024 + j + 2] * w_out[(j + 2)*256 + k];
        a3 += w_bot[m*1024 + j + 3] * w_out[(j + 3)*256 + k];
    }
    g_weff[m*256 + k] = (a0 + a1) + (a2 + a3);
    if (k == 0) {
        float bb = b_bot[m];
        for (int j = 0; j < 512; j++) bb += w_bot[m*1024 + j] * b_out[j];
        g_beff[m] = bb;
    }
}

// ---------------- operand pre-split kernels (fp32 -> bf16 hi/lo) ------------------
__global__ void splitA0_kernel(const float* __restrict__ w_kq)
{
    int m = blockIdx.x;      // 0..255
    for (int k = threadIdx.x; k < 512; k += 256) {
        unsigned short h, l; bf16split(w_kq[m*512 + k], h, l);
        g_A0h[m*512 + k] = h; g_A0l[m*512 + k] = l;
    }
}
__global__ void splitA1_kernel(const float* __restrict__ w_bot)
{
    int m = blockIdx.x;
    for (int k = threadIdx.x; k < 768; k += 256) {
        float v = (k < 256) ? g_weff[m*256 + k] : w_bot[m*1024 + 256 + k];
        unsigned short h, l; bf16split(v, h, l);
        g_A1h[m*768 + k] = h; g_A1l[m*768 + k] = l;
    }
}
__global__ void split_feats_kernel(const float* __restrict__ f)
{
    const size_t N4 = (size_t)BATCH*512*HW/4;
    for (size_t t = (size_t)blockIdx.x*blockDim.x + threadIdx.x;
         t < N4; t += (size_t)gridDim.x*blockDim.x) {
        float4 v = ((const float4*)f)[t];
        unsigned short h0,h1,h2,h3,l0,l1,l2,l3;
        bf16split(v.x,h0,l0); bf16split(v.y,h1,l1);
        bf16split(v.z,h2,l2); bf16split(v.w,h3,l3);
        ((uint2*)g_fh)[t] = make_uint2((uint32_t)h0 | ((uint32_t)h1<<16),
                                       (uint32_t)h2 | ((uint32_t)h3<<16));
        ((uint2*)g_fl)[t] = make_uint2((uint32_t)l0 | ((uint32_t)l1<<16),
                                       (uint32_t)l2 | ((uint32_t)l3<<16));
    }
}

// ================= TMA-fed mma.sync bf16 3-split GEMM =============================
// CTA tile 128m x 256n, 16 warps (each 64m x 32n), BK=64, 2-stage TMA pipeline.
// MODE 0: A = w_kq (256m), B = feats -> q = relu(.+b_kq) -> g_q fp32 + qh/ql bf16.
// MODE 1: A = [Weff | Wbot_right] (512m), B = [ctx; feats] -> out fp32.
#define A_BYTES 16384
#define STAGE_B 98304
#define CHUNK_TX 98304u

template<int MODE>
__global__ __launch_bounds__(512, 1)
void mma_gemm_kernel(const __grid_constant__ CUtensorMap tmAh,
                     const __grid_constant__ CUtensorMap tmAl,
                     const __grid_constant__ CUtensorMap tmBh,
                     const __grid_constant__ CUtensorMap tmBl,
                     const __grid_constant__ CUtensorMap tmB2h,
                     const __grid_constant__ CUtensorMap tmB2l,
                     const float* __restrict__ b_kq,
                     float* __restrict__ out)
{
    constexpr int K  = (MODE == 0) ? 512 : 768;
    constexpr int NC = K / 64;
    extern __shared__ char dyn[];
    char* base = (char*)(((uintptr_t)dyn + 1023) & ~(uintptr_t)1023);
    __shared__ alignas(8) unsigned long long s_mbar[2];

    const int tid  = threadIdx.x;
    const int wid  = tid >> 5, lane = tid & 31;
    const int wm   = wid & 1,  wn   = wid >> 1;       // wn 0..7
    const int m0   = blockIdx.x * 128;                // x = m-tile (L2 reuse of B)
    const int n0   = blockIdx.y * 256;
    const int b    = blockIdx.z;
    const int lr   = lane & 15, lh = lane >> 4;

    if (tid == 0) { mbar_init(smem_u32(&s_mbar[0]), 1); mbar_init(smem_u32(&s_mbar[1]), 1); }
    __syncthreads();
    if (tid == 0) fence_proxy_async_cta();
    __syncthreads();

    float acc[4][4][4];
#pragma unroll
    for (int i = 0; i < 4; i++)
#pragma unroll
        for (int j = 0; j < 4; j++)
#pragma unroll
            for (int r = 0; r < 4; r++) acc[i][j][r] = 0.f;

    auto issue_chunk = [&](int c) {
        const int buf = c & 1;
        const int k0  = c * 64;
        uint32_t sa = smem_u32(base + buf * STAGE_B);
        uint32_t mb = smem_u32(&s_mbar[buf]);
        mbar_expect_tx(mb, CHUNK_TX);
        tma2d(sa,           &tmAh, k0, m0, mb);
        tma2d(sa + A_BYTES, &tmAl, k0, m0, mb);
        const CUtensorMap *bh, *bl; int y;
        if (MODE == 0)     { bh = &tmBh;  bl = &tmBl;  y = b*512 + k0; }
        else if (k0 < 256) { bh = &tmBh;  bl = &tmBl;  y = b*256 + k0; }        // ctx
        else               { bh = &tmB2h; bl = &tmB2l; y = b*512 + (k0 - 256); } // feats
#pragma unroll
        for (int s = 0; s < 4; s++) {
            tma2d(sa + 2*A_BYTES + s*8192,         bh, n0 + 64*s, y, mb);
            tma2d(sa + 2*A_BYTES + 32768 + s*8192, bl, n0 + 64*s, y, mb);
        }
    };

    auto compute = [&](int c) {
        uint32_t aH = smem_u32(base + (c & 1) * STAGE_B);
        uint32_t aL = aH + A_BYTES;
        uint32_t bH = aL + A_BYTES;
        uint32_t bL = bH + 32768;
#pragma unroll
        for (int kk = 0; kk < 4; kk++) {
            const int k0 = kk * 16;
            uint32_t ah[4][4], al[4][4];
#pragma unroll
            for (int mi = 0; mi < 4; mi++) {
                int row = wm*64 + mi*16 + lr;
                uint32_t off = swz((uint32_t)(row*128 + (k0 + lh*8)*2));
                ldsm4(ah[mi], aH + off);
                ldsm4(al[mi], aL + off);
            }
            uint32_t bh[2][4], bl[2][4];
#pragma unroll
            for (int p = 0; p < 2; p++) {
                int n = wn*32 + p*16 + lh*8;
                uint32_t off = (uint32_t)((n >> 6) * 8192)
                             + swz((uint32_t)((k0 + lr)*128 + (n & 63)*2));
                ldsm4t(bh[p], bH + off);
                ldsm4t(bl[p], bL + off);
            }
#pragma unroll
            for (int mi = 0; mi < 4; mi++)
#pragma unroll
                for (int nj = 0; nj < 4; nj++) {
                    int p = nj >> 1, q = (nj & 1) * 2;
                    mma16816(acc[mi][nj], ah[mi], bh[p][q], bh[p][q+1]);
                }
#pragma unroll
            for (int mi = 0; mi < 4; mi++)
#pragma unroll
                for (int nj = 0; nj < 4; nj++) {
                    int p = nj >> 1, q = (nj & 1) * 2;
                    mma16816(acc[mi][nj], ah[mi], bl[p][q], bl[p][q+1]);
                }
#pragma unroll
            for (int mi = 0; mi < 4; mi++)
#pragma unroll
                for (int nj = 0; nj < 4; nj++) {
                    int p = nj >> 1, q = (nj & 1) * 2;
                    mma16816(acc[mi][nj], al[mi], bh[p][q], bh[p][q+1]);
                }
        }
    };

    if (tid == 0) { issue_chunk(0); issue_chunk(1); }
    for (int c = 0; c < NC; c++) {
        mbar_wait(smem_u32(&s_mbar[c & 1]), (uint32_t)((c >> 1) & 1));
        compute(c);
        __syncthreads();
        if (tid == 0 && c + 2 < NC) issue_chunk(c + 2);
    }

    // ---- epilogue: frags -> smem [128][260] -> coalesced gmem + bias/relu ----
    float* sD = (float*)base;
    {
        int tq = lane & 3, tr = lane >> 2;
#pragma unroll
        for (int mi = 0; mi < 4; mi++)
#pragma unroll
            for (int nj = 0; nj < 4; nj++) {
                int r0 = wm*64 + mi*16 + tr;
                int cc = wn*32 + nj*8 + tq*2;
                *(float2*)&sD[(size_t)r0*260 + cc]     = make_float2(acc[mi][nj][0], acc[mi][nj][1]);
                *(float2*)&sD[(size_t)(r0+8)*260 + cc] = make_float2(acc[mi][nj][2], acc[mi][nj][3]);
            }
    }
    __syncthreads();
#pragma unroll
    for (int u = 0; u < 16; u++) {
        int idx4 = tid + 512 * u;            // 0..8191
        int m = idx4 >> 6;                   // 0..127
        int n = (idx4 & 63) * 4;             // 0..252
        int mg = m0 + m;
        if (MODE == 0) {
            float bias = b_kq[mg];
            float4 o;
            o.x = fmaxf(sD[(size_t)m*260 + n + 0] + bias, 0.f);
            o.y = fmaxf(sD[(size_t)m*260 + n + 1] + bias, 0.f);
            o.z = fmaxf(sD[(size_t)m*260 + n + 2] + bias, 0.f);
            o.w = fmaxf(sD[(size_t)m*260 + n + 3] + bias, 0.f);
            size_t off = ((size_t)b*256 + mg)*HW + n0 + n;
            *(float4*)(g_q + off) = o;
            unsigned short h0,l0,h1,l1,h2,l2,h3,l3;
            bf16split(o.x,h0,l0); bf16split(o.y,h1,l1);
            bf16split(o.z,h2,l2); bf16split(o.w,h3,l3);
            *(uint2*)(g_qh + off) = make_uint2((uint32_t)h0 | ((uint32_t)h1<<16),
                                               (uint32_t)h2 | ((uint32_t)h3<<16));
            *(uint2*)(g_ql + off) = make_uint2((uint32_t)l0 | ((uint32_t)l1<<16),
                                               (uint32_t)l2 | ((uint32_t)l3<<16));
        } else {
            float bias = g_beff[mg];
            float* dst = out + ((size_t)b*512 + mg) * HW;
            float4 o;
            o.x = fmaxf(sD[(size_t)m*260 + n + 0] + bias, 0.f);
            o.y = fmaxf(sD[(size_t)m*260 + n + 1] + bias, 0.f);
            o.z = fmaxf(sD[(size_t)m*260 + n + 2] + bias, 0.f);
            o.w = fmaxf(sD[(size_t)m*260 + n + 3] + bias, 0.f);
            *(float4*)(dst + n0 + n) = o;
        }
    }
}

// ---------------- adaptive pooling (q -> key bf16, feats -> fpool fp32) -----------
// grid (768, BATCH): cc<256 -> q channel (from g_q fp32); cc>=256 -> feats channel
// (from ORIGINAL fp32 feats). Proven coalesced fp32 load pattern.
__global__ void poolqf_kernel(const float* __restrict__ feats)
{
    extern __shared__ float P[];   // [128][129]
    const int b = blockIdx.y, cc = blockIdx.x;
    const int t = threadIdx.x;     // 0..127
    const bool isq = (cc < 256);
    const float* src = isq ? (g_q + ((size_t)b*256 + cc)*HW)
                           : (feats + ((size_t)b*512 + (cc - 256))*HW);

    for (int i = 0; i < 128; i++) P[i*129 + t] = src[i*128 + t];
    __syncthreads();
    { float s = 0.f;
      for (int j = 0; j < 128; j++) { s += P[t*129 + j]; P[t*129 + j] = s; } }
    __syncthreads();
    { float s = 0.f;
      for (int i = 0; i < 128; i++) { s += P[i*129 + t]; P[i*129 + t] = s; } }
    __syncthreads();
    if (t < 112) {
        float avg = 0.f;
        if (t < 110) {
            int sidx = t, sc, idx;
            if      (sidx == 0) { sc = 1; idx = 0; }
            else if (sidx < 10) { sc = 3; idx = sidx - 1; }
            else if (sidx < 46) { sc = 6; idx = sidx - 10; }
            else                { sc = 8; idx = sidx - 46; }
            int i = idx / sc, j = idx % sc;
            int h0 = (i*128)/sc, h1 = ((i+1)*128 + sc - 1)/sc;
            int w0 = (j*128)/sc, w1 = ((j+1)*128 + sc - 1)/sc;
            float s11 =                      P[(h1-1)*129 + (w1-1)];
            float s01 = (h0 > 0)           ? P[(h0-1)*129 + (w1-1)] : 0.f;
            float s10 = (w0 > 0)           ? P[(h1-1)*129 + (w0-1)] : 0.f;
            float s00 = (h0 > 0 && w0 > 0) ? P[(h0-1)*129 + (w0-1)] : 0.f;
            avg = (s11 - s01 - s10 + s00) / (float)((h1 - h0)*(w1 - w0));
        }
        if (isq) {
            unsigned short hh, ll; bf16split(avg, hh, ll);
            size_t o = ((size_t)b*256 + cc)*112 + t;
            g_keyh[o] = hh; g_keyl[o] = ll;
        } else {
            g_fpool[((size_t)b*112 + t)*512 + (cc - 256)] = avg;
        }
    }
}

// ---------------- v-pool: valt = Wv @ fpool + b_v  (pooling commuted) -------------
// grid (112, BATCH), 256 threads (c). fpool reads coalesced ([s][c] layout).
__global__ void vpool_kernel(const float* __restrict__ w_v, const float* __restrict__ b_v)
{
    __shared__ float fp[512];
    const int s = blockIdx.x, b = blockIdx.y;
    const int c = threadIdx.x;
    unsigned short hh = 0, ll = 0;
    if (s < 110) {
        const float* row = g_fpool + ((size_t)b*112 + s)*512;
        fp[c]       = row[c];
        fp[c + 256] = row[c + 256];
        __syncthreads();
        float a0 = b_v[c], a1 = 0.f, a2 = 0.f, a3 = 0.f;
        const float* wr = w_v + (size_t)c*512;
#pragma unroll 4
        for (int k = 0; k < 512; k += 4) {
            a0 += wr[k+0] * fp[k+0];
            a1 += wr[k+1] * fp[k+1];
            a2 += wr[k+2] * fp[k+2];
            a3 += wr[k+3] * fp[k+3];
        }
        bf16split((a0 + a1) + (a2 + a3), hh, ll);
    }
    size_t o = ((size_t)b*112 + s)*256 + c;
    g_valth[o] = hh; g_valtl[o] = ll;
}

// ================= tensor-core attention (unchanged) ==============================
__global__ __launch_bounds__(256, 1)
void attn_kernel()
{
    extern __shared__ char smraw[];
    char* base = (char*)(((uintptr_t)smraw + 1023) & ~(uintptr_t)1023);
    float*    sim = (float*)base;                  // [128][120]
    ushort_t* Ah  = (ushort_t*)(base + 61440);     // [128][120]
    ushort_t* Al  = (ushort_t*)(base + 92160);
    char*     st1 = base + 61440;                  // phase1 staging, 2 x 17408
    char*     st2 = base + 122880;                 // valt staging,   2 x 8704

    const int b   = blockIdx.y;
    const int n0  = blockIdx.x * 128;
    const int tid = threadIdx.x;
    const int wid = tid >> 5, lane = tid & 31;
    const int lr  = lane & 15, lh = lane >> 4;
    const int mb  = (wid & 3) * 32;
    const int nb  = (wid >> 2) * 64;

    const ushort_t* gqh = g_qh + ((size_t)b*256)*HW + n0;
    const ushort_t* gql = g_ql + ((size_t)b*256)*HW + n0;
    const ushort_t* gkh = g_keyh + (size_t)b*256*112;
    const ushort_t* gkl = g_keyl + (size_t)b*256*112;

    {
        int i = tid;
        int stg  = i >> 7;
        int comp = (i >> 6) & 1;
        int row  = (i >> 2) & 15;
        int q8   = i & 3;
        *(uint2*)(st1 + stg*17408 + 8704 + comp*4352 + row*272 + 224 + q8*8)
            = make_uint2(0u, 0u);
    }
    __syncthreads();

    auto load_stage1 = [&](int c) {
        uint32_t sa = smem_u32(st1 + (c & 1) * 17408);
        const int c0 = c * 16;
#pragma unroll
        for (int u = 0; u < 4; u++) {
            int id = tid + 256*u;
            if (id < 512) {
                int comp = id >> 8, row = (id >> 4) & 15, c16 = id & 15;
                const ushort_t* src = (comp ? gql : gqh) + (size_t)(c0 + row)*HW + c16*8;
                cp16(sa + comp*4352 + row*272 + c16*16, src);
            } else if (id < 960) {
                int idx = id - 512;
                int comp = idx / 224;
                int rem  = idx - comp*224;
                int row  = rem / 14, c16 = rem - row*14;
                const ushort_t* src = (comp ? gkl : gkh) + (size_t)(c0 + row)*112 + c16*8;
                cp16(sa + 8704 + comp*4352 + row*272 + c16*16, src);
            }
        }
        cp_commit();
    };

    float acc[2][8][4];
#pragma unroll
    for (int i = 0; i < 2; i++)
#pragma unroll
        for (int j = 0; j < 8; j++)
#pragma unroll
            for (int r = 0; r < 4; r++) acc[i][j][r] = 0.f;

    load_stage1(0);
    for (int c = 0; c < 16; c++) {
        if (c + 1 < 16) { load_stage1(c + 1); cp_wait<1>(); }
        else            { cp_wait<0>(); }
        __syncthreads();
        uint32_t qa = smem_u32(st1 + (c & 1)*17408);
        uint32_t ka = qa + 8704;
        uint32_t ah[2][4], al[2][4], r4[4];
#pragma unroll
        for (int mi = 0; mi < 2; mi++) {
            uint32_t off = lr*272 + (mb + mi*16 + lh*8)*2;
            ldsm4t(r4, qa + off);
            ah[mi][0]=r4[0]; ah[mi][1]=r4[2]; ah[mi][2]=r4[1]; ah[mi][3]=r4[3];
            ldsm4t(r4, qa + 4352 + off);
            al[mi][0]=r4[0]; al[mi][1]=r4[2]; al[mi][2]=r4[1]; al[mi][3]=r4[3];
        }
        uint32_t bh[4][4], bl[4][4];
#pragma unroll
        for (int t = 0; t < 4; t++) {
            uint32_t off = lr*272 + (nb + t*16 + lh*8)*2;
            ldsm4t(bh[t], ka + off);
            ldsm4t(bl[t], ka + 4352 + off);
        }
#pragma unroll
        for (int mi = 0; mi < 2; mi++)
#pragma unroll
            for (int nj = 0; nj < 8; nj++) {
                int p = nj >> 1, q = (nj & 1)*2;
                mma16816(acc[mi][nj], ah[mi], bh[p][q], bh[p][q+1]);
            }
#pragma unroll
        for (int mi = 0; mi < 2; mi++)
#pragma unroll
            for (int nj = 0; nj < 8; nj++) {
                int p = nj >> 1, q = (nj & 1)*2;
                mma16816(acc[mi][nj], ah[mi], bl[p][q], bl[p][q+1]);
            }
#pragma unroll
        for (int mi = 0; mi < 2; mi++)
#pragma unroll
            for (int nj = 0; nj < 8; nj++) {
                int p = nj >> 1, q = (nj & 1)*2;
                mma16816(acc[mi][nj], al[mi], bh[p][q], bh[p][q+1]);
            }
        __syncthreads();
    }

#pragma unroll
    for (int mi = 0; mi < 2; mi++)
#pragma unroll
        for (int nj = 0; nj < 8; nj++) {
            int col = nb + nj*8 + (lane & 3)*2;
            if (col < 112) {
                int m = mb + mi*16 + (lane >> 2);
                sim[m*120 + col]       = acc[mi][nj][0] * 0.0625f;
                sim[m*120 + col + 1]   = acc[mi][nj][1] * 0.0625f;
                sim[(m+8)*120 + col]   = acc[mi][nj][2] * 0.0625f;
                sim[(m+8)*120 + col+1] = acc[mi][nj][3] * 0.0625f;
            }
        }
    __syncthreads();

    {
        int row = tid >> 1, half = tid & 1;
        float* r = sim + row*120;
        int s0 = half*55, s1 = s0 + 55;
        float mx = -1e30f;
        for (int s = s0; s < s1; s++) mx = fmaxf(mx, r[s]);
        mx = fmaxf(mx, __shfl_xor_sync(0xFFFFFFFFu, mx, 1));
        float sum = 0.f;
        for (int s = s0; s < s1; s++) { float e = __expf(r[s] - mx); r[s] = e; sum += e; }
        sum += __shfl_xor_sync(0xFFFFFFFFu, sum, 1);
        float inv = 1.f / sum;
        for (int s = s0; s < s1; s++) r[s] *= inv;
        if (half == 0) { r[110] = 0.f; r[111] = 0.f; }
    }
    __syncthreads();

    {
        int row = tid >> 1, h0 = (tid & 1)*56;
        for (int s = h0; s < h0 + 56; s++) {
            unsigned short hh, ll;
            bf16split(sim[row*120 + s], hh, ll);
            Ah[row*120 + s] = hh;
            Al[row*120 + s] = ll;
        }
    }
    __syncthreads();

    const ushort_t* gvh = g_valth + (size_t)b*112*256;
    const ushort_t* gvl = g_valtl + (size_t)b*112*256;
    const uint32_t Aaddr = smem_u32(Ah);
    const size_t cbase = (size_t)b*256*HW + n0;

    for (int hp = 0; hp < 2; hp++) {
        auto load_stage2 = [&](int s) {
            uint32_t sa = smem_u32(st2 + (s & 1)*8704);
            const int s0 = s * 16;
#pragma unroll
            for (int u = 0; u < 2; u++) {
                int id = tid + 256*u;         // 0..511
                int comp = id >> 8, row = (id >> 4) & 15, c16 = id & 15;
                const ushort_t* src = (comp ? gvl : gvh)
                    + (size_t)(s0 + row)*256 + hp*128 + c16*8;
                cp16(sa + comp*4352 + row*272 + c16*16, src);
            }
            cp_commit();
        };

        float acc2[2][8][4];
#pragma unroll
        for (int i = 0; i < 2; i++)
#pragma unroll
            for (int j = 0; j < 8; j++)
#pragma unroll
                for (int r = 0; r < 4; r++) acc2[i][j][r] = 0.f;

        load_stage2(0);
        for (int s = 0; s < 7; s++) {
            if (s + 1 < 7) { load_stage2(s + 1); cp_wait<1>(); }
            else           { cp_wait<0>(); }
            __syncthreads();
            uint32_t va = smem_u32(st2 + (s & 1)*8704);
            uint32_t ah2[2][4], al2[2][4];
#pragma unroll
            for (int mi = 0; mi < 2; mi++) {
                uint32_t off = (uint32_t)((mb + mi*16 + lr)*240 + (s*16 + lh*8)*2);
                ldsm4(ah2[mi], Aaddr + off);
                ldsm4(al2[mi], Aaddr + 30720 + off);
            }
            uint32_t bh2[4][4], bl2[4][4];
#pragma unroll
            for (int t = 0; t < 4; t++) {
                uint32_t off = lr*272 + (nb + t*16 + lh*8)*2;
                ldsm4t(bh2[t], va + off);
                ldsm4t(bl2[t], va + 4352 + off);
            }
#pragma unroll
            for (int mi = 0; mi < 2; mi++)
#pragma unroll
                for (int nj = 0; nj < 8; nj++) {
                    int p = nj >> 1, q = (nj & 1)*2;
                    mma16816(acc2[mi][nj], ah2[mi], bh2[p][q], bh2[p][q+1]);
                }
#pragma unroll
            for (int mi = 0; mi < 2; mi++)
#pragma unroll
                for (int nj = 0; nj < 8; nj++) {
                    int p = nj >> 1, q = (nj & 1)*2;
                    mma16816(acc2[mi][nj], ah2[mi], bl2[p][q], bl2[p][q+1]);
                }
#pragma unroll
            for (int mi = 0; mi < 2; mi++)
#pragma unroll
                for (int nj = 0; nj < 8; nj++) {
                    int p = nj >> 1, q = (nj & 1)*2;
                    mma16816(acc2[mi][nj], al2[mi], bh2[p][q], bh2[p][q+1]);
                }
            __syncthreads();
        }

#pragma unroll
        for (int mi = 0; mi < 2; mi++)
#pragma unroll
            for (int nj = 0; nj < 8; nj++) {
                int m = mb + mi*16 + (lane >> 2);
                int cch = hp*128 + nb + nj*8 + (lane & 3)*2;
                unsigned short hh, ll;
#pragma unroll
                for (int r = 0; r < 4; r++) {
                    int mm = m + (r >> 1)*8;
                    int cc = cch + (r & 1);
                    bf16split(acc2[mi][nj][r], hh, ll);
                    size_t o = cbase + (size_t)cc*HW + mm;
                    g_ctxh[o] = hh;
                    g_ctxl[o] = ll;
                }
            }
    }
}

// ------------------------- host-side TMA descriptor setup -------------------------
typedef CUresult (*PFN_encodeTiled)(
    CUtensorMap*, CUtensorMapDataType, unsigned int, void*,
    const unsigned long long*, const unsigned long long*,
    const unsigned int*, const unsigned int*,
    CUtensorMapInterleave, CUtensorMapSwizzle, CUtensorMapL2promotion,
    CUtensorMapFloatOOBfill);

static void enc2d(PFN_encodeTiled f, CUtensorMap* m, void* p,
                  unsigned long long rows, unsigned long long cols,
                  unsigned int box_inner, unsigned int box_rows)
{
    unsigned long long dims[2]    = {cols, rows};
    unsigned long long strides[1] = {cols * 2ull};     // u16
    unsigned int box[2]  = {box_inner, box_rows};
    unsigned int es[2]   = {1, 1};
    f(m, CU_TENSOR_MAP_DATA_TYPE_UINT16, 2, p, dims, strides, box, es,
      CU_TENSOR_MAP_INTERLEAVE_NONE, CU_TENSOR_MAP_SWIZZLE_128B,
      CU_TENSOR_MAP_L2_PROMOTION_L2_128B, CU_TENSOR_MAP_FLOAT_OOB_FILL_NONE);
}

// ----------------------------------------------------------------------------------
extern "C" void kernel_launch(void* const* d_in, const int* in_sizes, int n_in,
                              void* d_out, int out_size)
{
    const float* feats = (const float*)d_in[0];
    const float* w_kq  = (const float*)d_in[1];
    const float* b_kq  = (const float*)d_in[2];
    const float* w_v   = (const float*)d_in[3];
    const float* b_v   = (const float*)d_in[4];
    const float* w_out = (const float*)d_in[5];
    const float* b_out = (const float*)d_in[6];
    const float* w_bot = (const float*)d_in[7];
    const float* b_bot = (const float*)d_in[8];
    float* out = (float*)d_out;

    PFN_encodeTiled encf = nullptr;
    {
        void* fp = nullptr;
        cudaDriverEntryPointQueryResult st;
        cudaGetDriverEntryPoint("cuTensorMapEncodeTiled", &fp, cudaEnableDefault, &st);
        encf = (PFN_encodeTiled)fp;
    }
    void *pA0h, *pA0l, *pA1h, *pA1l, *pFh, *pFl, *pCh, *pCl;
    cudaGetSymbolAddress(&pA0h, g_A0h);  cudaGetSymbolAddress(&pA0l, g_A0l);
    cudaGetSymbolAddress(&pA1h, g_A1h);  cudaGetSymbolAddress(&pA1l, g_A1l);
    cudaGetSymbolAddress(&pFh,  g_fh);   cudaGetSymbolAddress(&pFl,  g_fl);
    cudaGetSymbolAddress(&pCh,  g_ctxh); cudaGetSymbolAddress(&pCl,  g_ctxl);

    CUtensorMap mA0h, mA0l, mA1h, mA1l, mFh, mFl, mCh, mCl;
    enc2d(encf, &mA0h, pA0h, 256, 512, 64, 128);
    enc2d(encf, &mA0l, pA0l, 256, 512, 64, 128);
    enc2d(encf, &mA1h, pA1h, 512, 768, 64, 128);
    enc2d(encf, &mA1l, pA1l, 512, 768, 64, 128);
    enc2d(encf, &mFh,  pFh,  (unsigned long long)BATCH*512, HW, 64, 64);
    enc2d(encf, &mFl,  pFl,  (unsigned long long)BATCH*512, HW, 64, 64);
    enc2d(encf, &mCh,  pCh,  (unsigned long long)BATCH*256, HW, 64, 64);
    enc2d(encf, &mCl,  pCl,  (unsigned long long)BATCH*256, HW, 64, 64);

    const int pool_smem = 128*129*4;                 // 66048
    const int attn_smem = 157696 + 1024;             // 158720
    const int mma_smem  = 2*STAGE_B + 1024;          // 197632
    cudaFuncSetAttribute(poolqf_kernel, cudaFuncAttributeMaxDynamicSharedMemorySize, pool_smem);
    cudaFuncSetAttribute(attn_kernel, cudaFuncAttributeMaxDynamicSharedMemorySize, attn_smem);
    cudaFuncSetAttribute(mma_gemm_kernel<0>, cudaFuncAttributeMaxDynamicSharedMemorySize, mma_smem);
    cudaFuncSetAttribute(mma_gemm_kernel<1>, cudaFuncAttributeMaxDynamicSharedMemorySize, mma_smem);

    weff_kernel<<<512, 256>>>(w_out, b_out, w_bot, b_bot);
    splitA0_kernel<<<256, 256>>>(w_kq);
    splitA1_kernel<<<512, 256>>>(w_bot);
    split_feats_kernel<<<4096, 256>>>(feats);
    mma_gemm_kernel<0><<<dim3(2, 64, BATCH), 512, mma_smem>>>(
        mA0h, mA0l, mFh, mFl, mFh, mFl, b_kq, out);
    poolqf_kernel<<<dim3(768, BATCH), 128, pool_smem>>>(feats);
    vpool_kernel<<<dim3(112, BATCH), 256>>>(w_v, b_v);
    attn_kernel<<<dim3(128, BATCH), 256, attn_smem>>>();
    mma_gemm_kernel<1><<<dim3(4, 64, BATCH), 512, mma_smem>>>(
        mA1h, mA1l, mCh, mCl, mFh, mFl, b_kq, out);
}